// round 9
// baseline (speedup 1.0000x reference)
#include <cuda_runtime.h>
#include <cstdint>

// Problem constants
#define C_IN      128
#define H_IN      112
#define W_IN      112
#define N_BATCH   8
#define HO_OUT    56
#define WO_OUT    56

// Tiling
#define TILE_WO   28
#define NTHREADS  512
#define GRID      148
#define NTILES    (N_BATCH * HO_OUT * 2)     // 896
#define ROW_S     58
#define CH_STRIDE 175                         // 3*58 + 1 pad (odd mod 32 -> conflict-free)

#define XBUF_FLOATS (C_IN * CH_STRIDE)        // 22400
#define NPART       32
#define RED_FLOATS  (NPART * 9 * TILE_WO)     // 8064
#define SIG_FLOATS  (9 * TILE_WO)             // 252
#define SMEM_FLOATS (2 * XBUF_FLOATS + RED_FLOATS + SIG_FLOATS + TILE_WO)
#define SMEM_BYTES  (SMEM_FLOATS * 4)         // 212,688 B

// Repacked weights: [c][i*3+j][12] (k contiguous, padded 9->12 for LDG.128)
__device__ __align__(16) float g_wpk[C_IN * 9 * 12];
__device__ float g_scale[9];
__device__ float g_shift[9];

__global__ void repack_kernel(const float* __restrict__ cw,
                              const float* __restrict__ bnw,
                              const float* __restrict__ bnb,
                              const float* __restrict__ bnm,
                              const float* __restrict__ bnv)
{
    int idx = blockIdx.x * blockDim.x + threadIdx.x;
    if (idx < C_IN * 81) {
        int c  = idx / 81;
        int r  = idx - c * 81;
        int k  = r / 9;
        int ij = r - k * 9;
        g_wpk[(c * 9 + ij) * 12 + k] = cw[(k * C_IN + c) * 9 + ij];
    }
    if (idx < 9) {
        float sc = bnw[idx] * rsqrtf(bnv[idx] + 1e-5f);
        g_scale[idx] = sc;
        g_shift[idx] = bnb[idx] - bnm[idx] * sc;
    }
}

// ---- f32x2 helpers (sm_103a packed fp32) ------------------------------------
__device__ __forceinline__ unsigned long long pk2(float v) {
    unsigned long long r;
    asm("mov.b64 %0, {%1, %1};" : "=l"(r) : "f"(v));
    return r;
}
__device__ __forceinline__ void ffma2(unsigned long long& d,
                                      unsigned long long a, unsigned long long b) {
    asm("fma.rn.f32x2 %0, %1, %2, %0;" : "+l"(d) : "l"(a), "l"(b));
}
__device__ __forceinline__ unsigned long long add2(unsigned long long a,
                                                   unsigned long long b) {
    unsigned long long r;
    asm("add.rn.f32x2 %0, %1, %2;" : "=l"(r) : "l"(a), "l"(b));
    return r;
}
__device__ __forceinline__ void unpk(unsigned long long v, float& lo, float& hi) {
    asm("mov.b64 {%0, %1}, %2;" : "=f"(lo), "=f"(hi) : "l"(v));
}
__device__ __forceinline__ void cp_async4(unsigned saddr, const float* gaddr) {
    asm volatile("cp.async.ca.shared.global [%0], [%1], 4;\n"
                 :: "r"(saddr), "l"(gaddr));
}

// Issue the cp.async loads for one tile (no commit/wait here).
__device__ __forceinline__ void stage_tile(const float* __restrict__ x,
                                           float* __restrict__ xbuf,
                                           int tidx, int t)
{
    if (t >= 348) return;                    // 2 x 174 staging threads
    const int wt = tidx & 1;
    const int ho = (tidx >> 1) % HO_OUT;
    const int n  = tidx / (2 * HO_OUT);

    const int half = (t >= 174) ? 1 : 0;
    const int p    = t - half * 174;
    const int r    = p / ROW_S;
    const int s    = p - r * ROW_S;
    int rr = 2 * ho - 1 + r;  if (rr < 0) rr = -rr;             // never > 111
    int cc = 2 * (wt * TILE_WO) - 1 + s;
    if (cc < 0) cc = -cc;  if (cc > W_IN - 1) cc = 2 * (W_IN - 1) - cc;

    const float* gp = x + (size_t)n * C_IN * H_IN * W_IN + rr * W_IN + cc;
    unsigned sa = (unsigned)__cvta_generic_to_shared(xbuf + p);
#pragma unroll 8
    for (int c2 = 0; c2 < C_IN / 2; c2++) {
        const int c = half + 2 * c2;
        cp_async4(sa + (unsigned)(c * CH_STRIDE * 4), gp + (size_t)c * (H_IN * W_IN));
    }
}

__global__ __launch_bounds__(NTHREADS, 1)
void pasa_fused_kernel(const float* __restrict__ x, float* __restrict__ out)
{
    extern __shared__ float sm[];
    float* xb0  = sm;
    float* xb1  = sm + XBUF_FLOATS;
    float* sred = sm + 2 * XBUF_FLOATS;      // [32 part][9 k][28 wo]
    float* ssig = sred + RED_FLOATS;         // [9 k][28 wo] (unnormalized)
    float* sinv = ssig + SIG_FLOATS;         // [28]

    const int t    = threadIdx.x;
    const int wg   = t & 3;                  // 4 wo-groups of 7
    const int cg   = t >> 2;                 // channel 0..127
    const int lane = t & 31;
    const int warp = t >> 5;

    // Prologue: stage first tile
    int tidx = blockIdx.x;
    int sel  = 0;
    stage_tile(x, xb0, tidx, t);
    asm volatile("cp.async.commit_group;\n" ::: "memory");

    while (tidx < NTILES) {
        const int nxt = tidx + GRID;
        float* cur = sel ? xb1 : xb0;
        float* pre = sel ? xb0 : xb1;

        if (nxt < NTILES) {                  // prefetch next tile
            stage_tile(x, pre, nxt, t);
            asm volatile("cp.async.commit_group;\n" ::: "memory");
            asm volatile("cp.async.wait_group 1;\n" ::: "memory");
        } else {
            asm volatile("cp.async.wait_group 0;\n" ::: "memory");
        }
        __syncthreads();

        const int wt = tidx & 1;
        const int ho = (tidx >> 1) % HO_OUT;
        const int n  = tidx / (2 * HO_OUT);
        const int wo0 = wt * TILE_WO;

        // ---------------- Sigma conv: 1 channel/thread, FFMA2 k-pairs ----------
        unsigned long long A0[7], A1[7], A2[7], A3[7];
        float A8[7];
#pragma unroll
        for (int u = 0; u < 7; u++) { A0[u]=0ull; A1[u]=0ull; A2[u]=0ull; A3[u]=0ull; A8[u]=0.0f; }

        {
            const float* wrow = g_wpk + cg * 108;
            const float* xc   = cur + cg * CH_STRIDE + wg * 14;
#pragma unroll
            for (int i = 0; i < 3; i++) {
                float xr[15];
#pragma unroll
                for (int s = 0; s < 15; s++) xr[s] = xc[i * ROW_S + s];
#pragma unroll
                for (int j = 0; j < 3; j++) {
                    const int off = (i * 3 + j) * 12;
                    const ulonglong2 pA = *reinterpret_cast<const ulonglong2*>(wrow + off);
                    const ulonglong2 pB = *reinterpret_cast<const ulonglong2*>(wrow + off + 4);
                    const float      w8 = wrow[off + 8];
#pragma unroll
                    for (int u = 0; u < 7; u++) {
                        const float xv = xr[2 * u + j];
                        const unsigned long long x2 = pk2(xv);
                        ffma2(A0[u], x2, pA.x);
                        ffma2(A1[u], x2, pA.y);
                        ffma2(A2[u], x2, pB.x);
                        ffma2(A3[u], x2, pB.y);
                        A8[u] = fmaf(xv, w8, A8[u]);
                    }
                }
            }
        }

        // 2-level butterfly over lane bits 2,3 (4 channels) -> 32 partials
#pragma unroll
        for (int u = 0; u < 7; u++) {
            unsigned long long v;
            v = A0[u]; v = add2(v, __shfl_xor_sync(0xffffffffu, v, 4)); v = add2(v, __shfl_xor_sync(0xffffffffu, v, 8)); A0[u] = v;
            v = A1[u]; v = add2(v, __shfl_xor_sync(0xffffffffu, v, 4)); v = add2(v, __shfl_xor_sync(0xffffffffu, v, 8)); A1[u] = v;
            v = A2[u]; v = add2(v, __shfl_xor_sync(0xffffffffu, v, 4)); v = add2(v, __shfl_xor_sync(0xffffffffu, v, 8)); A2[u] = v;
            v = A3[u]; v = add2(v, __shfl_xor_sync(0xffffffffu, v, 4)); v = add2(v, __shfl_xor_sync(0xffffffffu, v, 8)); A3[u] = v;
            float f = A8[u];
            f += __shfl_xor_sync(0xffffffffu, f, 4);
            f += __shfl_xor_sync(0xffffffffu, f, 8);
            A8[u] = f;
        }

        if ((lane & 12) == 0) {              // lanes {0..3, 16..19}
            const int p = (warp << 1) | (lane >> 4);     // 32 partials
            float* rp = sred + p * 252 + wg * 7;
            float lo, hi;
#pragma unroll
            for (int u = 0; u < 7; u++) {
                unpk(A0[u], lo, hi); rp[0*28+u] = lo; rp[1*28+u] = hi;
                unpk(A1[u], lo, hi); rp[2*28+u] = lo; rp[3*28+u] = hi;
                unpk(A2[u], lo, hi); rp[4*28+u] = lo; rp[5*28+u] = hi;
                unpk(A3[u], lo, hi); rp[6*28+u] = lo; rp[7*28+u] = hi;
                rp[8*28+u] = A8[u];
            }
        }
        __syncthreads();

        // ---------------- 32-way reduce (packed) + frozen-BN + clamp -----------
        if (t < 126) {                       // each thread: 2 consecutive entries
            const unsigned long long* r64 = reinterpret_cast<const unsigned long long*>(sred);
            unsigned long long s2 = r64[t];
#pragma unroll
            for (int p = 1; p < NPART; p++) s2 = add2(s2, r64[p * 126 + t]);
            const int k = t / 14;            // pairs never straddle k (28 even)
            const float sc = g_scale[k], sh = g_shift[k];
            float lo, hi; unpk(s2, lo, hi);
            lo = fmaxf(fmaf(lo, sc, sh), 1e-4f);
            hi = fmaxf(fmaf(hi, sc, sh), 1e-4f);
            ssig[2 * t]     = lo;
            ssig[2 * t + 1] = hi;
        }
        __syncthreads();

        // ---------------- Per-position 1/sum --------------------------------------
        if (t < TILE_WO) {
            float sum = 0.0f;
#pragma unroll
            for (int k = 0; k < 9; k++) sum += ssig[k * TILE_WO + t];
            sinv[t] = 1.0f / sum;
        }
        __syncthreads();

        // ---------------- Apply: 448 threads, sigma hoisted, 8 ch each ------------
        if (t < 16 * TILE_WO) {
            const int cl  = t / TILE_WO;     // 0..15
            const int wol = t - cl * TILE_WO;
            float sig[9];
#pragma unroll
            for (int k = 0; k < 9; k++) sig[k] = ssig[k * TILE_WO + wol];
            const float inv = sinv[wol];

            const float* xc = cur + cl * CH_STRIDE + 2 * wol;
            float* ob = out + ((size_t)n * C_IN + cl) * (HO_OUT * WO_OUT)
                            + (size_t)ho * WO_OUT + wo0 + wol;
#pragma unroll 4
            for (int it = 0; it < 8; it++) {
                float r = 0.0f;
#pragma unroll
                for (int i = 0; i < 3; i++)
#pragma unroll
                    for (int j = 0; j < 3; j++)
                        r = fmaf(xc[i * ROW_S + j], sig[i * 3 + j], r);
                *ob = r * inv;
                xc += 16 * CH_STRIDE;
                ob += (size_t)16 * HO_OUT * WO_OUT;
            }
        }
        __syncthreads();                     // cur buffer free for next prefetch

        tidx = nxt;
        sel ^= 1;
    }
}

extern "C" void kernel_launch(void* const* d_in, const int* in_sizes, int n_in,
                              void* d_out, int out_size)
{
    const float* x   = (const float*)d_in[0];
    const float* cw  = (const float*)d_in[1];
    const float* bnw = (const float*)d_in[2];
    const float* bnb = (const float*)d_in[3];
    const float* bnm = (const float*)d_in[4];
    const float* bnv = (const float*)d_in[5];
    float* out = (float*)d_out;

    repack_kernel<<<(C_IN * 81 + 255) / 256, 256>>>(cw, bnw, bnb, bnm, bnv);

    cudaFuncSetAttribute(pasa_fused_kernel,
                         cudaFuncAttributeMaxDynamicSharedMemorySize, SMEM_BYTES);
    pasa_fused_kernel<<<GRID, NTHREADS, SMEM_BYTES>>>(x, out);
}

// round 11
// speedup vs baseline: 1.4693x; 1.4693x over previous
#include <cuda_runtime.h>
#include <cstdint>

// Problem constants
#define C_IN      128
#define H_IN      112
#define W_IN      112
#define N_BATCH   8
#define HO_OUT    56
#define WO_OUT    56

// Tiling (R6 skeleton: 896 tiles, 256 threads, 2 CTAs/SM)
#define TILE_WO    28
#define NTHREADS   256
#define ROW_STRIDE 60                        // floats per staged row (mult of 4)
// CH_STRIDE = exact per-channel footprint (3*60 = 180, mult of 4).
// 180 mod 32 = 20, gcd(20,32)=4 -> channel bases cycle all 8 four-float bank
// residues: a free swizzle, no padding, no overlap. Sigma-phase conflict N=2.
#define CH_STRIDE  180
#define CBASE(c)   ((c) * CH_STRIDE)

#define XBUF_FLOATS (C_IN * CH_STRIDE)       // 23040 (mult of 8 -> sred u64-aligned)
#define NPART       16
#define RED_FLOATS  (NPART * 9 * TILE_WO)    // 4032
#define SIG_FLOATS  (9 * TILE_WO)            // 252
#define SMEM_BYTES  ((XBUF_FLOATS + RED_FLOATS + SIG_FLOATS) * 4)   // 109,296 B

// Repacked weights: [c][i*3+j][12] (k contiguous, padded 9->12 for LDG.128)
__device__ __align__(16) float g_wpk[C_IN * 9 * 12];
__device__ float g_scale[9];
__device__ float g_shift[9];

__global__ void repack_kernel(const float* __restrict__ cw,
                              const float* __restrict__ bnw,
                              const float* __restrict__ bnb,
                              const float* __restrict__ bnm,
                              const float* __restrict__ bnv)
{
    int idx = blockIdx.x * blockDim.x + threadIdx.x;
    if (idx < C_IN * 81) {
        int c  = idx / 81;
        int r  = idx - c * 81;
        int k  = r / 9;
        int ij = r - k * 9;
        g_wpk[(c * 9 + ij) * 12 + k] = cw[(k * C_IN + c) * 9 + ij];
    }
    if (idx < 9) {
        float sc = bnw[idx] * rsqrtf(bnv[idx] + 1e-5f);
        g_scale[idx] = sc;
        g_shift[idx] = bnb[idx] - bnm[idx] * sc;
    }
}

// ---- f32x2 helpers (sm_103a packed fp32) ------------------------------------
__device__ __forceinline__ unsigned long long pk2(float v) {
    unsigned long long r;
    asm("mov.b64 %0, {%1, %1};" : "=l"(r) : "f"(v));
    return r;
}
__device__ __forceinline__ void ffma2(unsigned long long& d,
                                      unsigned long long a, unsigned long long b) {
    asm("fma.rn.f32x2 %0, %1, %2, %0;" : "+l"(d) : "l"(a), "l"(b));
}
__device__ __forceinline__ unsigned long long add2(unsigned long long a,
                                                   unsigned long long b) {
    unsigned long long r;
    asm("add.rn.f32x2 %0, %1, %2;" : "=l"(r) : "l"(a), "l"(b));
    return r;
}
__device__ __forceinline__ void unpk(unsigned long long v, float& lo, float& hi) {
    asm("mov.b64 {%0, %1}, %2;" : "=f"(lo), "=f"(hi) : "l"(v));
}
__device__ __forceinline__ void cp_async4(unsigned saddr, const float* gaddr) {
    asm volatile("cp.async.ca.shared.global [%0], [%1], 4;\n"
                 :: "r"(saddr), "l"(gaddr));
}
__device__ __forceinline__ void cp_async16(unsigned saddr, const float* gaddr) {
    asm volatile("cp.async.cg.shared.global [%0], [%1], 16;\n"
                 :: "r"(saddr), "l"(gaddr));
}

__global__ __launch_bounds__(NTHREADS, 2)
void pasa_fused_kernel(const float* __restrict__ x, float* __restrict__ out)
{
    extern __shared__ float sm[];
    float* sx   = sm;                        // x tile, CH_STRIDE-cycled banks
    float* sred = sm + XBUF_FLOATS;          // [16 part][9 k][28 wo]
    float* ssig = sred + RED_FLOATS;         // [9 k][28 wo]

    const int b   = blockIdx.x;              // 0..895
    const int wt  = b & 1;
    const int ho  = (b >> 1) % HO_OUT;
    const int n   = b / (2 * HO_OUT);
    const int wo0 = wt * TILE_WO;
    const int t   = threadIdx.x;
    const int lane = t & 31;
    const int warp = t >> 5;

    const float* xn = x + (size_t)n * C_IN * H_IN * W_IN;

    // ---------------- Stage x tile: 16B cp.async, 57-col window ------------------
    // Window w=0..56 lives at slot CBASE(c)+60r+3+w. w=0 is the left halo
    // (reflected), w=1..56 is one contiguous 16B-aligned gmem block (cols GB..GB+55).
    // No right halo (max window index is 56 -> never read).
    {
        const int h0 = 2 * ho - 1;
        const int GB = wt ? 56 : 0;          // aligned block start col
        const int HL = wt ? 55 : 1;          // left-halo source col (reflected)
        const int i  = lane & 15;            // 0..13 chunk, 14 halo, 15 idle
        const unsigned xb_sa = (unsigned)__cvta_generic_to_shared(sx);
#pragma unroll 4
        for (int j = 0; j < 24; j++) {
            const int rowidx = (warp * 24 + j) * 2 + (lane >> 4);   // 0..383
            const int c = rowidx / 3;
            const int r = rowidx - 3 * c;
            int rr = h0 + r;  if (rr < 0) rr = -rr;                 // top edge only
            const float* grow = xn + (size_t)c * (H_IN * W_IN) + rr * W_IN;
            const unsigned sa = xb_sa + (unsigned)((CBASE(c) + ROW_STRIDE * r) * 4);
            if (i < 14)       cp_async16(sa + 16 + (i << 4), grow + GB + 4 * i);
            else if (i == 14) cp_async4(sa + 12, grow + HL);
        }
    }
    asm volatile("cp.async.commit_group;\n" ::: "memory");
    asm volatile("cp.async.wait_group 0;\n" ::: "memory");
    __syncthreads();

    // ---------------- Sigma conv: FFMA2, k packed in pairs ----------------------
    // thread = (wg = t&3 : 4 groups of 7 wo) x (cg = t>>2 : 64 groups of 2 ch)
    const int wg = t & 3;
    const int cg = t >> 2;

    unsigned long long A0[7], A1[7], A2[7], A3[7];   // k pairs (0,1)(2,3)(4,5)(6,7)
    float A8[7];
#pragma unroll
    for (int u = 0; u < 7; u++) { A0[u]=0ull; A1[u]=0ull; A2[u]=0ull; A3[u]=0ull; A8[u]=0.0f; }

#pragma unroll
    for (int cc2 = 0; cc2 < 2; cc2++) {
        const int c = cg * 2 + cc2;
        const float* wrow = g_wpk + c * 108;
        const float* xc   = sx + CBASE(c) + 3 + wg * 14;
#pragma unroll
        for (int i = 0; i < 3; i++) {
            float xr[15];
#pragma unroll
            for (int s = 0; s < 15; s++) xr[s] = xc[i * ROW_STRIDE + s];
#pragma unroll
            for (int j = 0; j < 3; j++) {
                const int off = (i * 3 + j) * 12;
                const ulonglong2 pA = *reinterpret_cast<const ulonglong2*>(wrow + off);
                const ulonglong2 pB = *reinterpret_cast<const ulonglong2*>(wrow + off + 4);
                const float      w8 = wrow[off + 8];
#pragma unroll
                for (int u = 0; u < 7; u++) {
                    const float xv = xr[2 * u + j];
                    const unsigned long long x2 = pk2(xv);
                    ffma2(A0[u], x2, pA.x);
                    ffma2(A1[u], x2, pA.y);
                    ffma2(A2[u], x2, pB.x);
                    ffma2(A3[u], x2, pB.y);
                    A8[u] = fmaf(xv, w8, A8[u]);
                }
            }
        }
    }

    // ---------------- 2-level butterfly (lane bits 2,3) -------------------------
#pragma unroll
    for (int u = 0; u < 7; u++) {
        unsigned long long v;
        v = A0[u]; v = add2(v, __shfl_xor_sync(0xffffffffu, v, 4)); v = add2(v, __shfl_xor_sync(0xffffffffu, v, 8)); A0[u] = v;
        v = A1[u]; v = add2(v, __shfl_xor_sync(0xffffffffu, v, 4)); v = add2(v, __shfl_xor_sync(0xffffffffu, v, 8)); A1[u] = v;
        v = A2[u]; v = add2(v, __shfl_xor_sync(0xffffffffu, v, 4)); v = add2(v, __shfl_xor_sync(0xffffffffu, v, 8)); A2[u] = v;
        v = A3[u]; v = add2(v, __shfl_xor_sync(0xffffffffu, v, 4)); v = add2(v, __shfl_xor_sync(0xffffffffu, v, 8)); A3[u] = v;
        float f = A8[u];
        f += __shfl_xor_sync(0xffffffffu, f, 4);
        f += __shfl_xor_sync(0xffffffffu, f, 8);
        A8[u] = f;
    }

    // Lanes {0..3, 16..19} of each warp hold sums over 4 cg (= 8 channels)
    if ((lane & 12) == 0) {
        const int p = (warp << 1) | (lane >> 4);     // 16 partials
        float* rp = sred + p * 252 + wg * 7;         // p*252 + k*28 + wg*7+u
        float lo, hi;
#pragma unroll
        for (int u = 0; u < 7; u++) {
            unpk(A0[u], lo, hi); rp[0*28+u] = lo; rp[1*28+u] = hi;
            unpk(A1[u], lo, hi); rp[2*28+u] = lo; rp[3*28+u] = hi;
            unpk(A2[u], lo, hi); rp[4*28+u] = lo; rp[5*28+u] = hi;
            unpk(A3[u], lo, hi); rp[6*28+u] = lo; rp[7*28+u] = hi;
            rp[8*28+u] = A8[u];
        }
    }
    __syncthreads();

    // ---------------- 16-way reduce (packed) + frozen-BN + clamp -----------------
    if (t < 126) {                           // 2 consecutive entries per thread
        const unsigned long long* r64 = reinterpret_cast<const unsigned long long*>(sred);
        unsigned long long s2 = r64[t];
#pragma unroll
        for (int p = 1; p < NPART; p++) s2 = add2(s2, r64[p * 126 + t]);
        const int k = t / 14;                // pairs never straddle k
        const float sc = g_scale[k], sh = g_shift[k];
        float lo, hi; unpk(s2, lo, hi);
        lo = fmaxf(fmaf(lo, sc, sh), 1e-4f);
        hi = fmaxf(fmaf(hi, sc, sh), 1e-4f);
        ssig[2 * t]     = lo;
        ssig[2 * t + 1] = hi;
    }
    __syncthreads();

    // ---------------- Normalize over the 9 taps ----------------------------------
    if (t < TILE_WO) {
        float sum = 0.0f;
#pragma unroll
        for (int k = 0; k < 9; k++) sum += ssig[k * TILE_WO + t];
        const float inv = 1.0f / sum;
#pragma unroll
        for (int k = 0; k < 9; k++) ssig[k * TILE_WO + t] *= inv;
    }
    __syncthreads();

    // ---------------- Apply: 224 threads, sigma hoisted, 16 ch each --------------
    if (t < 8 * TILE_WO) {
        const int cl  = t / TILE_WO;         // 0..7
        const int wol = t - cl * TILE_WO;
        float sig[9];
#pragma unroll
        for (int k = 0; k < 9; k++) sig[k] = ssig[k * TILE_WO + wol];

        float* ob = out + ((size_t)n * C_IN + cl) * (HO_OUT * WO_OUT)
                        + (size_t)ho * WO_OUT + wo0 + wol;
#pragma unroll 4
        for (int it = 0; it < 16; it++) {
            const int c = cl + 8 * it;
            const float* xc = sx + CBASE(c) + 3 + 2 * wol;
            float r = 0.0f;
#pragma unroll
            for (int i = 0; i < 3; i++)
#pragma unroll
                for (int j = 0; j < 3; j++)
                    r = fmaf(xc[i * ROW_STRIDE + j], sig[i * 3 + j], r);
            ob[(size_t)(8 * it) * (HO_OUT * WO_OUT)] = r;
        }
    }
}

extern "C" void kernel_launch(void* const* d_in, const int* in_sizes, int n_in,
                              void* d_out, int out_size)
{
    const float* x   = (const float*)d_in[0];
    const float* cw  = (const float*)d_in[1];
    const float* bnw = (const float*)d_in[2];
    const float* bnb = (const float*)d_in[3];
    const float* bnm = (const float*)d_in[4];
    const float* bnv = (const float*)d_in[5];
    float* out = (float*)d_out;

    repack_kernel<<<(C_IN * 81 + 255) / 256, 256>>>(cw, bnw, bnb, bnm, bnv);

    cudaFuncSetAttribute(pasa_fused_kernel,
                         cudaFuncAttributeMaxDynamicSharedMemorySize, SMEM_BYTES);
    const int grid = N_BATCH * HO_OUT * 2;   // 896 blocks
    pasa_fused_kernel<<<grid, NTHREADS, SMEM_BYTES>>>(x, out);
}